// round 14
// baseline (speedup 1.0000x reference)
#include <cuda_runtime.h>
#include <cuda_fp16.h>
#include <cstdint>

#define Nn     5000
#define TST    5024          // fp32 buffer node stride
#define NF     33
#define NU     32
#define TENC   12
#define TDEC   12
#define BM     64
#define MT     79            // M tiles of 64
#define SPLITK 8
#define GGRID  (MT*SPLITK)   // 632
#define KT     79            // K tiles of 64
#define NSTG   5
#define ATILE_H 4096         // halfs per A tile (64x64, plain rows)
#define BSTG_H  2880         // halfs per B stage (40 rows x 72)
#define BSTG_B  5760         // bytes per B stage
#define DSMEM   (NSTG*BSTG_B)   // 28800 bytes

// ---------------- persistent device state ----------------
__device__ __half gAt[(long)MT*KT*ATILE_H];    // tiled fp16 adj (51MB), plain layout
__device__ __align__(16) float g_X0T[NF*TST];
__device__ __align__(16) float g_X1T[NF*TST];
__device__ __align__(16) float g_X2T[NF*TST];
__device__ __align__(16) float g_C0T[NF*TST];
__device__ __align__(16) float g_C1T[NF*TST];
__device__ __align__(16) float g_C2T[NF*TST];
// fp16 shadows in TILE layout: [kt][40 rows][72 halfs], pads zero
__device__ __align__(16) __half g_X0h[KT*BSTG_H];
__device__ __align__(16) __half g_X1h[KT*BSTG_H];
__device__ __align__(16) __half g_C0h[KT*BSTG_H];
__device__ __align__(16) __half g_C1h[KT*BSTG_H];
__device__ float g_hT[NU*TST];
__device__ float g_uT[NU*TST];
__device__ unsigned g_cnt0[MT];
__device__ unsigned g_cnt2[MT];

// ---------------- helpers ----------------
__device__ __forceinline__ unsigned su32(const void* p) {
    return (unsigned)__cvta_generic_to_shared(p);
}
// half-index of (feature c, node n) in a tile-layout X shadow
__device__ __forceinline__ int xh_idx(int c, int n) {
    int kt = n >> 6, kn = n & 63;
    return kt * BSTG_H + c * 72 + kn;
}
__device__ __forceinline__ void bulk_cp(unsigned dst, const void* src,
                                        unsigned bytes, unsigned mbar) {
    asm volatile("cp.async.bulk.shared::cluster.global.mbarrier::complete_tx::bytes "
                 "[%0], [%1], %2, [%3];"
                 :: "r"(dst), "l"(src), "r"(bytes), "r"(mbar) : "memory");
}
__device__ __forceinline__ void mbar_init(unsigned a, unsigned c) {
    asm volatile("mbarrier.init.shared.b64 [%0], %1;" :: "r"(a), "r"(c) : "memory");
}
__device__ __forceinline__ void mbar_expect(unsigned a, unsigned tx) {
    asm volatile("mbarrier.arrive.expect_tx.shared.b64 _, [%0], %1;"
                 :: "r"(a), "r"(tx) : "memory");
}
__device__ __forceinline__ void mbar_wait(unsigned a, unsigned ph) {
    asm volatile("{\n\t.reg .pred P;\n\t"
                 "W%=:\n\tmbarrier.try_wait.parity.acquire.cta.shared::cta.b64 P, [%0], %1, 0x989680;\n\t"
                 "@!P bra W%=;\n\t}" :: "r"(a), "r"(ph) : "memory");
}
__device__ __forceinline__ void mma_f16(float* c, unsigned a0, unsigned a1,
                                        unsigned a2, unsigned a3,
                                        unsigned b0, unsigned b1) {
    asm volatile("mma.sync.aligned.m16n8k16.row.col.f32.f16.f16.f32 "
                 "{%0,%1,%2,%3}, {%4,%5,%6,%7}, {%8,%9}, {%0,%1,%2,%3};"
                 : "+f"(c[0]), "+f"(c[1]), "+f"(c[2]), "+f"(c[3])
                 : "r"(a0), "r"(a1), "r"(a2), "r"(a3), "r"(b0), "r"(b1));
}

// ============================================================================
// fp16 mma GEMM: YT(f,r) += sum_k A(r,k) * Xh(f,k)
// A: direct LDG -> register fragments (no smem; zero cross-warp reuse anyway),
//    double-buffered depth 2. B: TMA-bulk 5-stage mbarrier ring (smem, reused
//    by 4 warps). 64 rows/CTA, split-K=8, 4 CTAs/SM. atomicAdd epilogue.
// sel 0/2: last split-K CTA per M-tile converts fp32 output -> fp16 shadow.
// ============================================================================
__global__ void __launch_bounds__(128, 4) gemm_mma(int sel)
{
    const __half* __restrict__ XH;
    float* __restrict__ YT;
    __half* __restrict__ DH = nullptr;
    unsigned* cnt = nullptr;
    switch (sel) {
        case 0:  XH = g_X0h; YT = g_X1T; DH = g_X1h; cnt = g_cnt0; break;
        case 1:  XH = g_X1h; YT = g_X2T; break;
        case 2:  XH = g_C0h; YT = g_C1T; DH = g_C1h; cnt = g_cnt2; break;
        default: XH = g_C1h; YT = g_C2T; break;
    }

    extern __shared__ char smc[];      // [5][B stage 5760B]
    __shared__ __align__(8) unsigned long long mbar[NSTG];
    __shared__ int isLast;

    const int t    = threadIdx.x;
    const int w    = t >> 5, lane = t & 31;
    const int r4   = lane >> 2, c4 = lane & 3;
    const int rt   = blockIdx.x % MT;
    const int ck   = blockIdx.x / MT;
    const int row0 = rt * BM;
    const int tS   = (KT * ck)       / SPLITK;
    const int tE   = (KT * (ck + 1)) / SPLITK;
    const int nt   = tE - tS;

    if (t == 0) {
        #pragma unroll
        for (int s = 0; s < NSTG; ++s) mbar_init(su32(&mbar[s]), 1);
    }
    asm volatile("fence.proxy.async.shared::cta;" ::: "memory");
    __syncthreads();

    // B prologue: 4 tiles in flight
    if (t == 0) {
        #pragma unroll
        for (int p = 0; p < 4; ++p) {
            if (p < nt) {
                unsigned mb = su32(&mbar[p]);
                mbar_expect(mb, BSTG_B);
                bulk_cp(su32(smc + p*BSTG_B), XH + (long)(tS+p)*BSTG_H, BSTG_B, mb);
            }
        }
    }

    // A fragment base for this thread: rows (w*16 + r4 / +8), k halfs 2*c4
    const __half* aBase = gAt + (long)rt*KT*ATILE_H + (w*16 + r4)*64 + 2*c4;

    auto ldA = [&](int tile, unsigned* f) {
        const __half* p = aBase + (long)tile*ATILE_H;
        #pragma unroll
        for (int ks = 0; ks < 4; ++ks) {
            f[ks*4+0] = *(const unsigned*)(p + ks*16);
            f[ks*4+1] = *(const unsigned*)(p + ks*16 + 8*64);
            f[ks*4+2] = *(const unsigned*)(p + ks*16 + 8);
            f[ks*4+3] = *(const unsigned*)(p + ks*16 + 8*64 + 8);
        }
    };

    float acc[5][4];
    #pragma unroll
    for (int ct = 0; ct < 5; ++ct)
        #pragma unroll
        for (int i = 0; i < 4; ++i) acc[ct][i] = 0.f;

    unsigned fA0[16], fA1[16];
    ldA(tS, fA0);
    if (nt > 1) ldA(tS + 1, fA1);

    const int bro = r4 * 72 + 2*c4;    // B half-offset for this lane (row r4 base)

    #define COMP(F)                                                            \
        _Pragma("unroll")                                                      \
        for (int ks = 0; ks < 4; ++ks) {                                       \
            _Pragma("unroll")                                                  \
            for (int ct = 0; ct < 5; ++ct) {                                   \
                unsigned b0 = *(const unsigned*)(bB + bro + ct*(8*72) + ks*16);\
                unsigned b1 = *(const unsigned*)(bB + bro + ct*(8*72) + ks*16 + 8);\
                mma_f16(acc[ct], (F)[ks*4], (F)[ks*4+1], (F)[ks*4+2], (F)[ks*4+3], b0, b1); \
            }                                                                  \
        }

    for (int i = 0; i < nt; ++i) {
        mbar_wait(su32(&mbar[i % NSTG]), (unsigned)(i / NSTG) & 1);
        __syncthreads();               // all warps done reading stage (i+4)%5 at iter i-1
        if (t == 0 && i + 4 < nt) {
            int s2 = (i + 4) % NSTG;
            unsigned mb = su32(&mbar[s2]);
            mbar_expect(mb, BSTG_B);
            bulk_cp(su32(smc + s2*BSTG_B), XH + (long)(tS+i+4)*BSTG_H, BSTG_B, mb);
        }
        const __half* bB = (const __half*)(smc + (i % NSTG) * BSTG_B);
        if ((i & 1) == 0) {
            COMP(fA0);
            if (i + 2 < nt) ldA(tS + i + 2, fA0);
        } else {
            COMP(fA1);
            if (i + 2 < nt) ldA(tS + i + 2, fA1);
        }
    }
    #undef COMP

    const int rA = row0 + w*16 + r4;
    const int rB = rA + 8;
    #pragma unroll
    for (int ct = 0; ct < 5; ++ct) {
        const int col0 = ct*8 + 2*c4;
        const int col1 = col0 + 1;
        if (col0 < NF) {
            if (rA < Nn) atomicAdd(YT + (long)col0*TST + rA, acc[ct][0]);
            if (rB < Nn) atomicAdd(YT + (long)col0*TST + rB, acc[ct][2]);
        }
        if (col1 < NF) {
            if (rA < Nn) atomicAdd(YT + (long)col1*TST + rA, acc[ct][1]);
            if (rB < Nn) atomicAdd(YT + (long)col1*TST + rB, acc[ct][3]);
        }
    }

    // fused fp32 -> fp16 tile-shadow conversion by the last split-K CTA
    if (DH) {
        __threadfence();
        if (t == 0) isLast = (atomicAdd(&cnt[rt], 1u) == SPLITK - 1);
        __syncthreads();
        if (isLast) {
            __threadfence();
            for (int idx = t; idx < BM * NF; idx += 128) {
                int c = idx >> 6, kn = idx & 63;
                int r = row0 + kn;
                if (r < Nn)
                    DH[xh_idx(c, r)] = __float2half_rn(YT[(long)c*TST + r]);
            }
            if (t == 0) cnt[rt] = 0;
        }
    }
}

// ============================================================================
// Prep: adj fp32 -> plain tiled fp16 (zero-padded). Warp = 2 tile rows.
// ============================================================================
__global__ void conv_A(const float* __restrict__ A) {
    const int lane = threadIdx.x & 31;
    const int rh = lane >> 4;             // 0..1 row within pair
    const int l16 = lane & 15;            // 4 cols each
    long gw0 = (long)blockIdx.x * 8 + (threadIdx.x >> 5);
    const long total = (long)MT * KT * 32;    // row-pairs
    for (long gw = gw0; gw < total; gw += (long)gridDim.x * 8) {
        int rp = (int)(gw & 31);
        long t2 = gw >> 5;
        int kt = (int)(t2 % KT);
        int mt = (int)(t2 / KT);
        int r = rp * 2 + rh;
        int grow = mt * 64 + r;
        int gk = kt * 64 + l16 * 4;
        float v0 = 0.f, v1 = 0.f, v2 = 0.f, v3 = 0.f;
        if (grow < Nn) {
            const float* src = A + (long)grow * Nn + gk;
            if (gk + 3 < Nn) {
                float4 vv = *(const float4*)src;
                v0 = vv.x; v1 = vv.y; v2 = vv.z; v3 = vv.w;
            } else {
                if (gk     < Nn) v0 = src[0];
                if (gk + 1 < Nn) v1 = src[1];
                if (gk + 2 < Nn) v2 = src[2];
                if (gk + 3 < Nn) v3 = src[3];
            }
        }
        __half2 h01 = __floats2half2_rn(v0, v1);
        __half2 h23 = __floats2half2_rn(v2, v3);
        char* dst = (char*)gAt + ((long)(mt*KT + kt))*8192 + r*128 + l16*8;
        ((unsigned*)dst)[0] = *(unsigned*)&h01;
        ((unsigned*)dst)[1] = *(unsigned*)&h23;
    }
}

// ============================================================================
// Elementwise kernels
// ============================================================================
__global__ void init_k() {
    int tid = blockIdx.x * blockDim.x + threadIdx.x;
    int nth = gridDim.x * blockDim.x;
    for (int j = tid; j < NF * TST; j += nth) {
        g_X0T[j] = 0.f; g_X1T[j] = 0.f; g_X2T[j] = 0.f;
        g_C0T[j] = 0.f; g_C1T[j] = 0.f; g_C2T[j] = 0.f;
    }
    for (int j = tid; j < KT * BSTG_H; j += nth) {
        g_X0h[j] = __half(0.f); g_X1h[j] = __half(0.f);
        g_C0h[j] = __half(0.f); g_C1h[j] = __half(0.f);
    }
    for (int j = tid; j < NU * TST; j += nth) { g_hT[j] = 0.f; g_uT[j] = 0.f; }
    for (int j = tid; j < MT; j += nth) { g_cnt0[j] = 0u; g_cnt2[j] = 0u; }
}

__global__ void build_enc(const float* __restrict__ inp, int tstep) {
    int tid = blockIdx.x * blockDim.x + threadIdx.x;
    int nth = gridDim.x * blockDim.x;
    for (int j = tid; j < NF * TST; j += nth) {
        int c = j / TST, n = j - c * TST;
        float v = 0.f;
        if (n < Nn) {
            v = (c == 0) ? inp[n * TENC + tstep] : g_hT[(c - 1) * TST + n];
            g_X0h[xh_idx(c, n)] = __float2half_rn(v);
        }
        g_X0T[j] = v;
        g_X1T[j] = 0.f; g_X2T[j] = 0.f;
    }
}

__global__ void build_dec0() {
    int tid = blockIdx.x * blockDim.x + threadIdx.x;
    int nth = gridDim.x * blockDim.x;
    for (int j = tid; j < NF * TST; j += nth) {
        int c = j / TST, n = j - c * TST;
        float v = 0.f;
        if (n < Nn) {
            if (c > 0) v = g_hT[(c - 1) * TST + n];
            g_X0h[xh_idx(c, n)] = __float2half_rn(v);
        }
        g_X0T[j] = v;
        g_X1T[j] = 0.f; g_X2T[j] = 0.f;
    }
}

__global__ void __launch_bounds__(256) gate_k(const float* __restrict__ W,
                                              const float* __restrict__ b) {
    __shared__ float sW[99 * 64];
    __shared__ float sx[99 * 32];
    const int t = threadIdx.x, lane = t & 31, w = t >> 5;
    const int rowb = blockIdx.x * 32;
    for (int j = t; j < 99 * 64; j += 256) sW[j] = W[j];
    for (int j = t; j < 99 * 32; j += 256) {
        int c = j >> 5, i = j & 31;
        const float* src = (c < 33) ? (g_X0T + c * TST)
                         : (c < 66) ? (g_X1T + (c - 33) * TST)
                                    : (g_X2T + (c - 66) * TST);
        sx[j] = src[rowb + i];
    }
    __syncthreads();

    float acc[8];
    #pragma unroll
    for (int cc = 0; cc < 8; ++cc) acc[cc] = b[8 * w + cc];
    for (int k = 0; k < 99; ++k) {
        float xv = sx[k * 32 + lane];
        const float4* wr = reinterpret_cast<const float4*>(sW + k * 64 + 8 * w);
        float4 w0 = wr[0], w1 = wr[1];
        acc[0] = fmaf(xv, w0.x, acc[0]); acc[1] = fmaf(xv, w0.y, acc[1]);
        acc[2] = fmaf(xv, w0.z, acc[2]); acc[3] = fmaf(xv, w0.w, acc[3]);
        acc[4] = fmaf(xv, w1.x, acc[4]); acc[5] = fmaf(xv, w1.y, acc[5]);
        acc[6] = fmaf(xv, w1.z, acc[6]); acc[7] = fmaf(xv, w1.w, acc[7]);
    }
    int row = rowb + lane;
    if (row < Nn) {
        #pragma unroll
        for (int cc = 0; cc < 8; ++cc) {
            int col = 8 * w + cc;
            float s = 1.f / (1.f + expf(-acc[cc]));
            if (col < 32) {
                float rh = s * g_hT[col * TST + row];
                g_C0T[(1 + col) * TST + row] = rh;
                g_C0h[xh_idx(1 + col, row)] = __float2half_rn(rh);
            } else {
                g_uT[(col - 32) * TST + row] = s;
            }
        }
        if (w == 0) {
            float x0 = g_X0T[row];
            g_C0T[row] = x0;
            g_C0h[xh_idx(0, row)] = __float2half_rn(x0);
        }
    }
    int tid = blockIdx.x * 256 + t, nth = gridDim.x * 256;
    for (int j = tid; j < NF * TST; j += nth) { g_C1T[j] = 0.f; g_C2T[j] = 0.f; }
}

__global__ void __launch_bounds__(256) cand_k(const float* __restrict__ W,
                                              const float* __restrict__ b) {
    __shared__ float sW[99 * 32];
    __shared__ float sx[99 * 32];
    const int t = threadIdx.x, lane = t & 31, w = t >> 5;
    const int rowb = blockIdx.x * 32;
    for (int j = t; j < 99 * 32; j += 256) sW[j] = W[j];
    for (int j = t; j < 99 * 32; j += 256) {
        int c = j >> 5, i = j & 31;
        const float* src = (c < 33) ? (g_C0T + c * TST)
                         : (c < 66) ? (g_C1T + (c - 33) * TST)
                                    : (g_C2T + (c - 66) * TST);
        sx[j] = src[rowb + i];
    }
    __syncthreads();

    float acc[4];
    #pragma unroll
    for (int cc = 0; cc < 4; ++cc) acc[cc] = b[4 * w + cc];
    for (int k = 0; k < 99; ++k) {
        float xv = sx[k * 32 + lane];
        float4 wv = *reinterpret_cast<const float4*>(sW + k * 32 + 4 * w);
        acc[0] = fmaf(xv, wv.x, acc[0]); acc[1] = fmaf(xv, wv.y, acc[1]);
        acc[2] = fmaf(xv, wv.z, acc[2]); acc[3] = fmaf(xv, wv.w, acc[3]);
    }
    int row = rowb + lane;
    if (row < Nn) {
        #pragma unroll
        for (int cc = 0; cc < 4; ++cc) {
            int col = 4 * w + cc;
            float c = tanhf(acc[cc]);
            float u = g_uT[col * TST + row];
            float h = g_hT[col * TST + row];
            g_hT[col * TST + row] = u * h + (1.f - u) * c;
        }
    }
}

__global__ void __launch_bounds__(256) dec_post(const float* __restrict__ Wp,
                                                const float* __restrict__ bp,
                                                float* __restrict__ out, int tstep) {
    int tid = blockIdx.x * 256 + threadIdx.x;
    int nth = gridDim.x * 256;
    for (int row = tid; row < Nn; row += nth) {
        float acc = bp[0];
        #pragma unroll
        for (int c = 0; c < 32; ++c) acc = fmaf(g_hT[c * TST + row], Wp[c], acc);
        out[row * TDEC + tstep] = acc;
        g_X0T[row] = acc;
        g_X0h[xh_idx(0, row)] = __float2half_rn(acc);
    }
    for (int j = tid; j < NU * TST; j += nth) {
        int c = j / TST, n = j - c * TST;
        float h = g_hT[j];
        g_X0T[TST + j] = h;
        if (n < Nn) g_X0h[xh_idx(1 + c, n)] = __float2half_rn(h);
    }
    for (int j = tid; j < NF * TST; j += nth) { g_X1T[j] = 0.f; g_X2T[j] = 0.f; }
}

// ============================================================================
// Host launch sequence
// ============================================================================
extern "C" void kernel_launch(void* const* d_in, const int* in_sizes, int n_in,
                              void* d_out, int out_size) {
    const float* inputs = (const float*)d_in[0];
    const float* adj    = (const float*)d_in[2];
    const float* enc_Wg = (const float*)d_in[3];
    const float* enc_bg = (const float*)d_in[4];
    const float* enc_Wc = (const float*)d_in[5];
    const float* enc_bc = (const float*)d_in[6];
    const float* dec_Wg = (const float*)d_in[7];
    const float* dec_bg = (const float*)d_in[8];
    const float* dec_Wc = (const float*)d_in[9];
    const float* dec_bc = (const float*)d_in[10];
    const float* dec_Wp = (const float*)d_in[11];
    const float* dec_bp = (const float*)d_in[12];
    float* out = (float*)d_out;

    cudaFuncSetAttribute(gemm_mma, cudaFuncAttributeMaxDynamicSharedMemorySize, DSMEM);

    conv_A<<<4096, 256>>>(adj);
    init_k<<<256, 256>>>();

    for (int t = 0; t < TENC; ++t) {
        build_enc<<<256, 256>>>(inputs, t);
        gemm_mma<<<GGRID, 128, DSMEM>>>(0);
        gemm_mma<<<GGRID, 128, DSMEM>>>(1);
        gate_k<<<157, 256>>>(enc_Wg, enc_bg);
        gemm_mma<<<GGRID, 128, DSMEM>>>(2);
        gemm_mma<<<GGRID, 128, DSMEM>>>(3);
        cand_k<<<157, 256>>>(enc_Wc, enc_bc);
    }

    build_dec0<<<256, 256>>>();
    for (int t = 0; t < TDEC; ++t) {
        gemm_mma<<<GGRID, 128, DSMEM>>>(0);
        gemm_mma<<<GGRID, 128, DSMEM>>>(1);
        gate_k<<<157, 256>>>(dec_Wg, dec_bg);
        gemm_mma<<<GGRID, 128, DSMEM>>>(2);
        gemm_mma<<<GGRID, 128, DSMEM>>>(3);
        cand_k<<<157, 256>>>(dec_Wc, dec_bc);
        dec_post<<<157, 256>>>(dec_Wp, dec_bp, out, t);
    }
}

// round 15
// speedup vs baseline: 1.5727x; 1.5727x over previous
#include <cuda_runtime.h>
#include <cuda_fp16.h>
#include <cstdint>

#define Nn     5000
#define TST    5024          // fp32 buffer node stride
#define NF     33
#define NU     32
#define TENC   12
#define TDEC   12
#define BM     64
#define MT     79            // M tiles of 64
#define SPLITK 7
#define GGRID  (MT*SPLITK)   // 553
#define KT     79            // K tiles of 64
#define NSTG   5
#define BSTG_H  2880         // halfs per B stage (40 rows x 72)
#define BSTG_B  5760         // bytes per B stage
#define DSMEM   (NSTG*BSTG_B)   // 28800 bytes

// ---------------- persistent device state ----------------
// adj as fp16 in FRAGMENT-MAJOR tiles: tile(mt,kt) = 512 uint4;
// offset (uint4) = w*128 + ks*32 + lane; payload = {a0,a1,a2,a3} for that thread.
__device__ uint4 gAt[(long)MT*KT*512];         // 51MB
__device__ __align__(16) float g_X0T[NF*TST];
__device__ __align__(16) float g_X1T[NF*TST];
__device__ __align__(16) float g_X2T[NF*TST];
__device__ __align__(16) float g_C0T[NF*TST];
__device__ __align__(16) float g_C1T[NF*TST];
__device__ __align__(16) float g_C2T[NF*TST];
// fp16 shadows in TILE layout: [kt][40 rows][72 halfs], pads zero
__device__ __align__(16) __half g_X0h[KT*BSTG_H];
__device__ __align__(16) __half g_X1h[KT*BSTG_H];
__device__ __align__(16) __half g_C0h[KT*BSTG_H];
__device__ __align__(16) __half g_C1h[KT*BSTG_H];
__device__ float g_hT[NU*TST];
__device__ float g_uT[NU*TST];
__device__ unsigned g_cnt0[MT];
__device__ unsigned g_cnt2[MT];

// ---------------- helpers ----------------
__device__ __forceinline__ unsigned su32(const void* p) {
    return (unsigned)__cvta_generic_to_shared(p);
}
__device__ __forceinline__ int xh_idx(int c, int n) {
    int kt = n >> 6, kn = n & 63;
    return kt * BSTG_H + c * 72 + kn;
}
__device__ __forceinline__ void bulk_cp(unsigned dst, const void* src,
                                        unsigned bytes, unsigned mbar) {
    asm volatile("cp.async.bulk.shared::cluster.global.mbarrier::complete_tx::bytes "
                 "[%0], [%1], %2, [%3];"
                 :: "r"(dst), "l"(src), "r"(bytes), "r"(mbar) : "memory");
}
__device__ __forceinline__ void mbar_init(unsigned a, unsigned c) {
    asm volatile("mbarrier.init.shared.b64 [%0], %1;" :: "r"(a), "r"(c) : "memory");
}
__device__ __forceinline__ void mbar_expect(unsigned a, unsigned tx) {
    asm volatile("mbarrier.arrive.expect_tx.shared.b64 _, [%0], %1;"
                 :: "r"(a), "r"(tx) : "memory");
}
__device__ __forceinline__ void mbar_wait(unsigned a, unsigned ph) {
    asm volatile("{\n\t.reg .pred P;\n\t"
                 "W%=:\n\tmbarrier.try_wait.parity.acquire.cta.shared::cta.b64 P, [%0], %1, 0x989680;\n\t"
                 "@!P bra W%=;\n\t}" :: "r"(a), "r"(ph) : "memory");
}
__device__ __forceinline__ void mma_f16(float* c, unsigned a0, unsigned a1,
                                        unsigned a2, unsigned a3,
                                        unsigned b0, unsigned b1) {
    asm volatile("mma.sync.aligned.m16n8k16.row.col.f32.f16.f16.f32 "
                 "{%0,%1,%2,%3}, {%4,%5,%6,%7}, {%8,%9}, {%0,%1,%2,%3};"
                 : "+f"(c[0]), "+f"(c[1]), "+f"(c[2]), "+f"(c[3])
                 : "r"(a0), "r"(a1), "r"(a2), "r"(a3), "r"(b0), "r"(b1));
}

// ============================================================================
// fp16 mma GEMM: YT(f,r) += sum_k A(r,k) * Xh(f,k)
// A: fragment-major tiles -> 4 coalesced LDG.128/thread/tile straight into
//    registers (no smem), double-buffered. B: TMA-bulk 5-stage mbarrier ring.
// 64 rows/CTA, split-K=7, 4 CTAs/SM. atomicAdd epilogue.
// sel 0/2: last split-K CTA per M-tile converts fp32 output -> fp16 shadow.
// ============================================================================
__global__ void __launch_bounds__(128, 4) gemm_mma(int sel)
{
    const __half* __restrict__ XH;
    float* __restrict__ YT;
    __half* __restrict__ DH = nullptr;
    unsigned* cnt = nullptr;
    switch (sel) {
        case 0:  XH = g_X0h; YT = g_X1T; DH = g_X1h; cnt = g_cnt0; break;
        case 1:  XH = g_X1h; YT = g_X2T; break;
        case 2:  XH = g_C0h; YT = g_C1T; DH = g_C1h; cnt = g_cnt2; break;
        default: XH = g_C1h; YT = g_C2T; break;
    }

    extern __shared__ char smc[];      // [5][B stage 5760B]
    __shared__ __align__(8) unsigned long long mbar[NSTG];
    __shared__ int isLast;

    const int t    = threadIdx.x;
    const int w    = t >> 5, lane = t & 31;
    const int r4   = lane >> 2, c4 = lane & 3;
    const int rt   = blockIdx.x % MT;
    const int ck   = blockIdx.x / MT;
    const int row0 = rt * BM;
    const int tS   = (KT * ck)       / SPLITK;
    const int tE   = (KT * (ck + 1)) / SPLITK;
    const int nt   = tE - tS;

    if (t == 0) {
        #pragma unroll
        for (int s = 0; s < NSTG; ++s) mbar_init(su32(&mbar[s]), 1);
    }
    asm volatile("fence.proxy.async.shared::cta;" ::: "memory");
    __syncthreads();

    // B prologue: 4 tiles in flight
    if (t == 0) {
        #pragma unroll
        for (int p = 0; p < 4; ++p) {
            if (p < nt) {
                unsigned mb = su32(&mbar[p]);
                mbar_expect(mb, BSTG_B);
                bulk_cp(su32(smc + p*BSTG_B), XH + (long)(tS+p)*BSTG_H, BSTG_B, mb);
            }
        }
    }

    // A fragment pointer for this thread (uint4 units)
    const uint4* aBase = gAt + (long)rt*KT*512 + w*128 + lane;

    auto ldA = [&](int tile, uint4* f) {
        const uint4* p = aBase + (long)tile*512;
        #pragma unroll
        for (int ks = 0; ks < 4; ++ks) f[ks] = p[ks*32];
    };

    float acc[5][4];
    #pragma unroll
    for (int ct = 0; ct < 5; ++ct)
        #pragma unroll
        for (int i = 0; i < 4; ++i) acc[ct][i] = 0.f;

    uint4 fA0[4], fA1[4];
    ldA(tS, fA0);
    if (nt > 1) ldA(tS + 1, fA1);

    const int bro = r4 * 72 + 2*c4;    // B half-offset for this lane

    #define COMP(F)                                                            \
        _Pragma("unroll")                                                      \
        for (int ks = 0; ks < 4; ++ks) {                                       \
            _Pragma("unroll")                                                  \
            for (int ct = 0; ct < 5; ++ct) {                                   \
                unsigned b0 = *(const unsigned*)(bB + bro + ct*(8*72) + ks*16);\
                unsigned b1 = *(const unsigned*)(bB + bro + ct*(8*72) + ks*16 + 8);\
                mma_f16(acc[ct], (F)[ks].x, (F)[ks].y, (F)[ks].z, (F)[ks].w, b0, b1); \
            }                                                                  \
        }

    for (int i = 0; i < nt; ++i) {
        mbar_wait(su32(&mbar[i % NSTG]), (unsigned)(i / NSTG) & 1);
        __syncthreads();               // stage (i+4)%5 free (read finished iter i-1)
        if (t == 0 && i + 4 < nt) {
            int s2 = (i + 4) % NSTG;
            unsigned mb = su32(&mbar[s2]);
            mbar_expect(mb, BSTG_B);
            bulk_cp(su32(smc + s2*BSTG_B), XH + (long)(tS+i+4)*BSTG_H, BSTG_B, mb);
        }
        const __half* bB = (const __half*)(smc + (i % NSTG) * BSTG_B);
        if ((i & 1) == 0) {
            COMP(fA0);
            if (i + 2 < nt) ldA(tS + i + 2, fA0);
        } else {
            COMP(fA1);
            if (i + 2 < nt) ldA(tS + i + 2, fA1);
        }
    }
    #undef COMP

    const int rA = row0 + w*16 + r4;
    const int rB = rA + 8;
    #pragma unroll
    for (int ct = 0; ct < 5; ++ct) {
        const int col0 = ct*8 + 2*c4;
        const int col1 = col0 + 1;
        if (col0 < NF) {
            if (rA < Nn) atomicAdd(YT + (long)col0*TST + rA, acc[ct][0]);
            if (rB < Nn) atomicAdd(YT + (long)col0*TST + rB, acc[ct][2]);
        }
        if (col1 < NF) {
            if (rA < Nn) atomicAdd(YT + (long)col1*TST + rA, acc[ct][1]);
            if (rB < Nn) atomicAdd(YT + (long)col1*TST + rB, acc[ct][3]);
        }
    }

    // fused fp32 -> fp16 tile-shadow conversion by the last split-K CTA
    if (DH) {
        __threadfence();
        if (t == 0) isLast = (atomicAdd(&cnt[rt], 1u) == SPLITK - 1);
        __syncthreads();
        if (isLast) {
            __threadfence();
            for (int idx = t; idx < BM * NF; idx += 128) {
                int c = idx >> 6, kn = idx & 63;
                int r = row0 + kn;
                if (r < Nn)
                    DH[xh_idx(c, r)] = __float2half_rn(YT[(long)c*TST + r]);
            }
            if (t == 0) cnt[rt] = 0;
        }
    }
}

// ============================================================================
// Prep: adj fp32 -> fragment-major fp16 tiles (zero-padded OOB).
// One warp per (tile, w, ks) 512B group; lane builds its own 16B fragment.
// ============================================================================
__global__ void conv_A(const float* __restrict__ A) {
    const int lane = threadIdx.x & 31;
    const int r4 = lane >> 2, c4 = lane & 3;
    long gw0 = (long)blockIdx.x * 8 + (threadIdx.x >> 5);
    const long total = (long)MT * KT * 16;   // tile x wgroup x ks
    for (long gw = gw0; gw < total; gw += (long)gridDim.x * 8) {
        int ks = (int)(gw & 3);
        long t1 = gw >> 2;
        int wg = (int)(t1 & 3);
        long t2 = t1 >> 2;
        int kt = (int)(t2 % KT);
        int mt = (int)(t2 / KT);
        int gr0 = mt*64 + wg*16 + r4;
        int gr1 = gr0 + 8;
        int kc  = kt*64 + ks*16 + 2*c4;

        float v00=0.f, v01=0.f, v10=0.f, v11=0.f;   // a0: (gr0,kc..kc+1); a1: (gr1,...)
        float w00=0.f, w01=0.f, w10=0.f, w11=0.f;   // a2: (gr0,kc+8..9);  a3: (gr1,...)
        if (gr0 < Nn) {
            const float* s = A + (long)gr0 * Nn;
            if (kc     < Nn) v00 = s[kc];
            if (kc + 1 < Nn) v01 = s[kc + 1];
            if (kc + 8 < Nn) w00 = s[kc + 8];
            if (kc + 9 < Nn) w01 = s[kc + 9];
        }
        if (gr1 < Nn) {
            const float* s = A + (long)gr1 * Nn;
            if (kc     < Nn) v10 = s[kc];
            if (kc + 1 < Nn) v11 = s[kc + 1];
            if (kc + 8 < Nn) w10 = s[kc + 8];
            if (kc + 9 < Nn) w11 = s[kc + 9];
        }
        __half2 a0 = __floats2half2_rn(v00, v01);
        __half2 a1 = __floats2half2_rn(v10, v11);
        __half2 a2 = __floats2half2_rn(w00, w01);
        __half2 a3 = __floats2half2_rn(w10, w11);
        uint4 frag;
        frag.x = *(unsigned*)&a0; frag.y = *(unsigned*)&a1;
        frag.z = *(unsigned*)&a2; frag.w = *(unsigned*)&a3;
        gAt[((long)(mt*KT + kt))*512 + wg*128 + ks*32 + lane] = frag;
    }
}

// ============================================================================
// Elementwise kernels
// ============================================================================
__global__ void init_k() {
    int tid = blockIdx.x * blockDim.x + threadIdx.x;
    int nth = gridDim.x * blockDim.x;
    for (int j = tid; j < NF * TST; j += nth) {
        g_X0T[j] = 0.f; g_X1T[j] = 0.f; g_X2T[j] = 0.f;
        g_C0T[j] = 0.f; g_C1T[j] = 0.f; g_C2T[j] = 0.f;
    }
    for (int j = tid; j < KT * BSTG_H; j += nth) {
        g_X0h[j] = __half(0.f); g_X1h[j] = __half(0.f);
        g_C0h[j] = __half(0.f); g_C1h[j] = __half(0.f);
    }
    for (int j = tid; j < NU * TST; j += nth) { g_hT[j] = 0.f; g_uT[j] = 0.f; }
    for (int j = tid; j < MT; j += nth) { g_cnt0[j] = 0u; g_cnt2[j] = 0u; }
}

__global__ void build_enc(const float* __restrict__ inp, int tstep) {
    int tid = blockIdx.x * blockDim.x + threadIdx.x;
    int nth = gridDim.x * blockDim.x;
    for (int j = tid; j < NF * TST; j += nth) {
        int c = j / TST, n = j - c * TST;
        float v = 0.f;
        if (n < Nn) {
            v = (c == 0) ? inp[n * TENC + tstep] : g_hT[(c - 1) * TST + n];
            g_X0h[xh_idx(c, n)] = __float2half_rn(v);
        }
        g_X0T[j] = v;
        g_X1T[j] = 0.f; g_X2T[j] = 0.f;
    }
}

__global__ void build_dec0() {
    int tid = blockIdx.x * blockDim.x + threadIdx.x;
    int nth = gridDim.x * blockDim.x;
    for (int j = tid; j < NF * TST; j += nth) {
        int c = j / TST, n = j - c * TST;
        float v = 0.f;
        if (n < Nn) {
            if (c > 0) v = g_hT[(c - 1) * TST + n];
            g_X0h[xh_idx(c, n)] = __float2half_rn(v);
        }
        g_X0T[j] = v;
        g_X1T[j] = 0.f; g_X2T[j] = 0.f;
    }
}

__global__ void __launch_bounds__(256) gate_k(const float* __restrict__ W,
                                              const float* __restrict__ b) {
    __shared__ float sW[99 * 64];
    __shared__ float sx[99 * 32];
    const int t = threadIdx.x, lane = t & 31, w = t >> 5;
    const int rowb = blockIdx.x * 32;
    for (int j = t; j < 99 * 64; j += 256) sW[j] = W[j];
    for (int j = t; j < 99 * 32; j += 256) {
        int c = j >> 5, i = j & 31;
        const float* src = (c < 33) ? (g_X0T + c * TST)
                         : (c < 66) ? (g_X1T + (c - 33) * TST)
                                    : (g_X2T + (c - 66) * TST);
        sx[j] = src[rowb + i];
    }
    __syncthreads();

    float acc[8];
    #pragma unroll
    for (int cc = 0; cc < 8; ++cc) acc[cc] = b[8 * w + cc];
    for (int k = 0; k < 99; ++k) {
        float xv = sx[k * 32 + lane];
        const float4* wr = reinterpret_cast<const float4*>(sW + k * 64 + 8 * w);
        float4 w0 = wr[0], w1 = wr[1];
        acc[0] = fmaf(xv, w0.x, acc[0]); acc[1] = fmaf(xv, w0.y, acc[1]);
        acc[2] = fmaf(xv, w0.z, acc[2]); acc[3] = fmaf(xv, w0.w, acc[3]);
        acc[4] = fmaf(xv, w1.x, acc[4]); acc[5] = fmaf(xv, w1.y, acc[5]);
        acc[6] = fmaf(xv, w1.z, acc[6]); acc[7] = fmaf(xv, w1.w, acc[7]);
    }
    int row = rowb + lane;
    if (row < Nn) {
        #pragma unroll
        for (int cc = 0; cc < 8; ++cc) {
            int col = 8 * w + cc;
            float s = 1.f / (1.f + expf(-acc[cc]));
            if (col < 32) {
                float rh = s * g_hT[col * TST + row];
                g_C0T[(1 + col) * TST + row] = rh;
                g_C0h[xh_idx(1 + col, row)] = __float2half_rn(rh);
            } else {
                g_uT[(col - 32) * TST + row] = s;
            }
        }
        if (w == 0) {
            float x0 = g_X0T[row];
            g_C0T[row] = x0;
            g_C0h[xh_idx(0, row)] = __float2half_rn(x0);
        }
    }
    int tid = blockIdx.x * 256 + t, nth = gridDim.x * 256;
    for (int j = tid; j < NF * TST; j += nth) { g_C1T[j] = 0.f; g_C2T[j] = 0.f; }
}

__global__ void __launch_bounds__(256) cand_k(const float* __restrict__ W,
                                              const float* __restrict__ b) {
    __shared__ float sW[99 * 32];
    __shared__ float sx[99 * 32];
    const int t = threadIdx.x, lane = t & 31, w = t >> 5;
    const int rowb = blockIdx.x * 32;
    for (int j = t; j < 99 * 32; j += 256) sW[j] = W[j];
    for (int j = t; j < 99 * 32; j += 256) {
        int c = j >> 5, i = j & 31;
        const float* src = (c < 33) ? (g_C0T + c * TST)
                         : (c < 66) ? (g_C1T + (c - 33) * TST)
                                    : (g_C2T + (c - 66) * TST);
        sx[j] = src[rowb + i];
    }
    __syncthreads();

    float acc[4];
    #pragma unroll
    for (int cc = 0; cc < 4; ++cc) acc[cc] = b[4 * w + cc];
    for (int k = 0; k < 99; ++k) {
        float xv = sx[k * 32 + lane];
        float4 wv = *reinterpret_cast<const float4*>(sW + k * 32 + 4 * w);
        acc[0] = fmaf(xv, wv.x, acc[0]); acc[1] = fmaf(xv, wv.y, acc[1]);
        acc[2] = fmaf(xv, wv.z, acc[2]); acc[3] = fmaf(xv, wv.w, acc[3]);
    }
    int row = rowb + lane;
    if (row < Nn) {
        #pragma unroll
        for (int cc = 0; cc < 4; ++cc) {
            int col = 4 * w + cc;
            float c = tanhf(acc[cc]);
            float u = g_uT[col * TST + row];
            float h = g_hT[col * TST + row];
            g_hT[col * TST + row] = u * h + (1.f - u) * c;
        }
    }
}

__global__ void __launch_bounds__(256) dec_post(const float* __restrict__ Wp,
                                                const float* __restrict__ bp,
                                                float* __restrict__ out, int tstep) {
    int tid = blockIdx.x * 256 + threadIdx.x;
    int nth = gridDim.x * 256;
    for (int row = tid; row < Nn; row += nth) {
        float acc = bp[0];
        #pragma unroll
        for (int c = 0; c < 32; ++c) acc = fmaf(g_hT[c * TST + row], Wp[c], acc);
        out[row * TDEC + tstep] = acc;
        g_X0T[row] = acc;
        g_X0h[xh_idx(0, row)] = __float2half_rn(acc);
    }
    for (int j = tid; j < NU * TST; j += nth) {
        int c = j / TST, n = j - c * TST;
        float h = g_hT[j];
        g_X0T[TST + j] = h;
        if (n < Nn) g_X0h[xh_idx(1 + c, n)] = __float2half_rn(h);
    }
    for (int j = tid; j < NF * TST; j += nth) { g_X1T[j] = 0.f; g_X2T[j] = 0.f; }
}

// ============================================================================
// Host launch sequence
// ============================================================================
extern "C" void kernel_launch(void* const* d_in, const int* in_sizes, int n_in,
                              void* d_out, int out_size) {
    const float* inputs = (const float*)d_in[0];
    const float* adj    = (const float*)d_in[2];
    const float* enc_Wg = (const float*)d_in[3];
    const float* enc_bg = (const float*)d_in[4];
    const float* enc_Wc = (const float*)d_in[5];
    const float* enc_bc = (const float*)d_in[6];
    const float* dec_Wg = (const float*)d_in[7];
    const float* dec_bg = (const float*)d_in[8];
    const float* dec_Wc = (const float*)d_in[9];
    const float* dec_bc = (const float*)d_in[10];
    const float* dec_Wp = (const float*)d_in[11];
    const float* dec_bp = (const float*)d_in[12];
    float* out = (float*)d_out;

    cudaFuncSetAttribute(gemm_mma, cudaFuncAttributeMaxDynamicSharedMemorySize, DSMEM);

    conv_A<<<4096, 256>>>(adj);
    init_k<<<256, 256>>>();

    for (int t = 0; t < TENC; ++t) {
        build_enc<<<256, 256>>>(inputs, t);
        gemm_mma<<<GGRID, 128, DSMEM>>>(0);
        gemm_mma<<<GGRID, 128, DSMEM>>>(1);
        gate_k<<<157, 256>>>(enc_Wg, enc_bg);
        gemm_mma<<<GGRID, 128, DSMEM>>>(2);
        gemm_mma<<<GGRID, 128, DSMEM>>>(3);
        cand_k<<<157, 256>>>(enc_Wc, enc_bc);
    }

    build_dec0<<<256, 256>>>();
    for (int t = 0; t < TDEC; ++t) {
        gemm_mma<<<GGRID, 128, DSMEM>>>(0);
        gemm_mma<<<GGRID, 128, DSMEM>>>(1);
        gate_k<<<157, 256>>>(dec_Wg, dec_bg);
        gemm_mma<<<GGRID, 128, DSMEM>>>(2);
        gemm_mma<<<GGRID, 128, DSMEM>>>(3);
        cand_k<<<157, 256>>>(dec_Wc, dec_bc);
        dec_post<<<157, 256>>>(dec_Wp, dec_bp, out, t);
    }
}